// round 11
// baseline (speedup 1.0000x reference)
#include <cuda_runtime.h>
#include <cuda_fp16.h>
#include <cstdint>

// Problem constants (fixed by setup_inputs)
#define TOKENS 16384
#define DIM    1024
#define CD     16
#define CS     8192

#define N_X  (TOKENS * DIM)
#define N_W  (CD * DIM)
#define N_CB (CS * CD)

// ---- scan tiling ----
#define CHUNK_N   128                 // codes per smem chunk
#define NCHUNK    (CS / CHUNK_N)      // 64
#define ROWB      112                 // bytes/code row: 56 halves (48 data + 8 pad)
#define CHUNK_B   (CHUNK_N * ROWB)    // 14336
#define SCAN_THREADS 512
#define KB        3                   // 3 K-groups of 16 (fp16 2-split: hh,hm,mh)

// dynamic smem layout (bytes)
#define OFF_B0   0
#define OFF_B1   CHUNK_B
#define OFF_HB0  (2 * CHUNK_B)               // 512 B
#define OFF_HB1  (2 * CHUNK_B + 512)
#define OFF_Z    (2 * CHUNK_B + 1024)        // 8 KB
#define OFF_RES  (OFF_Z + 128 * CD * 4)
#define SCAN_SMEM (OFF_RES + 128 * 8)

__device__ __align__(16) float g_z[TOKENS * CD];
__device__ float g_hbneg[CS];                               // -0.5*||c||^2
__device__ __align__(16) unsigned char g_img[CS * ROWB];    // 896KB split-codebook image

// ---------------- helpers ----------------
__device__ __forceinline__ uint32_t smem_u32(const void* p) {
    uint32_t a;
    asm("{ .reg .u64 t; cvta.to.shared.u64 t, %1; cvt.u32.u64 %0, t; }"
        : "=r"(a) : "l"(p));
    return a;
}
__device__ __forceinline__ void cpa16(uint32_t dst, const void* src) {
    asm volatile("cp.async.ca.shared.global [%0], [%1], 16;"
                 :: "r"(dst), "l"(src) : "memory");
}
__device__ __forceinline__ void cpa_commit() {
    asm volatile("cp.async.commit_group;" ::: "memory");
}
__device__ __forceinline__ void cpa_wait1() {
    asm volatile("cp.async.wait_group 1;" ::: "memory");
}
__device__ __forceinline__ void cpa_wait0() {
    asm volatile("cp.async.wait_group 0;" ::: "memory");
}
__device__ __forceinline__ unsigned int ordf(float f) {
    unsigned int u = __float_as_uint(f);
    return (u & 0x80000000u) ? ~u : (u | 0x80000000u);
}
// fp16 2-level split: v ~= h + m
__device__ __forceinline__ void split2(float f, unsigned short& h, unsigned short& m) {
    __half hh = __float2half_rn(f);
    float fh = __half2float(hh);
    __half mm = __float2half_rn(f - fh);
    h = *reinterpret_cast<unsigned short*>(&hh);
    m = *reinterpret_cast<unsigned short*>(&mm);
}
// product table per k-group kb (kb<3): (A,B) = (h,h),(h,m),(m,h)
__device__ __forceinline__ int lvlA(int kb) { return kb >> 1; }
__device__ __forceinline__ int lvlB(int kb) { return kb & 1; }

__device__ __forceinline__ void mma16816(float* d, const uint32_t* a,
                                         uint32_t b0, uint32_t b1) {
    asm volatile(
        "mma.sync.aligned.m16n8k16.row.col.f32.f16.f16.f32 "
        "{%0,%1,%2,%3},{%4,%5,%6,%7},{%8,%9},{%0,%1,%2,%3};"
        : "+f"(d[0]), "+f"(d[1]), "+f"(d[2]), "+f"(d[3])
        : "r"(a[0]), "r"(a[1]), "r"(a[2]), "r"(a[3]), "r"(b0), "r"(b1));
}

// ---------------- kernel 0a: -0.5*||c||^2 ----------------
__global__ void prep_kernel(const float* __restrict__ cb) {
    int k = blockIdx.x * blockDim.x + threadIdx.x;
    if (k < CS) {
        float s = 0.f;
#pragma unroll
        for (int i = 0; i < CD; i++) {
            float v = cb[(size_t)k * CD + i];
            s = fmaf(v, v, s);
        }
        g_hbneg[k] = -0.5f * s;
    }
}

// ---------------- kernel 0b: split codebook -> B-fragment image ----------------
__global__ void prep_image_kernel(const float* __restrict__ cb) {
    int idx = blockIdx.x * blockDim.x + threadIdx.x;
    if (idx >= CS * 4) return;
    int k = idx >> 2;
    int t = idx & 3;
    const float* row = cb + (size_t)k * CD;
    float c0 = row[2 * t],     c1 = row[2 * t + 1];
    float c8 = row[2 * t + 8], c9 = row[2 * t + 9];
    unsigned short h0, m0, h1, m1, h8, m8, h9, m9;
    split2(c0, h0, m0); split2(c1, h1, m1);
    split2(c8, h8, m8); split2(c9, h9, m9);
    uint32_t wh0 = (uint32_t)h0 | ((uint32_t)h1 << 16);
    uint32_t wh1 = (uint32_t)h8 | ((uint32_t)h9 << 16);
    uint32_t wm0 = (uint32_t)m0 | ((uint32_t)m1 << 16);
    uint32_t wm1 = (uint32_t)m8 | ((uint32_t)m9 << 16);
    uint32_t* base = reinterpret_cast<uint32_t*>(g_img + (size_t)k * ROWB);
#pragma unroll
    for (int kb = 0; kb < KB; kb++) {
        uint32_t* p = base + kb * 8 + t * 2;
        if (lvlB(kb)) { p[0] = wm0; p[1] = wm1; }
        else          { p[0] = wh0; p[1] = wh1; }
    }
    if (t == 0) {   // zero the 16-byte pad (positions 48..55)
        uint4 zz = {0u, 0u, 0u, 0u};
        *reinterpret_cast<uint4*>(base + 24) = zz;
    }
}

// ---------------- kernel 1: projection + LayerNorm (scalar, proven) ------------
#define P1_BLOCK  128
#define P1_DCHUNK 64
#define P1_XPAD   65

__global__ void __launch_bounds__(P1_BLOCK)
proj_ln_kernel(const float* __restrict__ x, const float* __restrict__ W) {
    __shared__ float xs[P1_BLOCK * P1_XPAD];
    __shared__ float wt[P1_DCHUNK][CD];

    const int tid = threadIdx.x;
    const int tokBase = blockIdx.x * P1_BLOCK;

    float z[CD];
#pragma unroll
    for (int c = 0; c < CD; c++) z[c] = 0.f;

    for (int dB = 0; dB < DIM; dB += P1_DCHUNK) {
        __syncthreads();
        for (int i = tid; i < P1_DCHUNK * CD; i += P1_BLOCK) {
            int d = i >> 4, c = i & 15;
            wt[d][c] = W[c * DIM + dB + d];
        }
        for (int it = 0; it < 16; it++) {
            int i = it * P1_BLOCK + tid;
            int row = i >> 4;
            int col = (i & 15) << 2;
            const float* src = x + (size_t)(tokBase + row) * DIM + dB + col;
            float* dst = xs + row * P1_XPAD + col;
            dst[0] = src[0]; dst[1] = src[1]; dst[2] = src[2]; dst[3] = src[3];
        }
        __syncthreads();

        const float* xr = xs + tid * P1_XPAD;
#pragma unroll 8
        for (int d = 0; d < P1_DCHUNK; d++) {
            float xv = xr[d];
#pragma unroll
            for (int c = 0; c < CD; c++)
                z[c] = fmaf(xv, wt[d][c], z[c]);
        }
    }

    float mu = 0.f;
#pragma unroll
    for (int c = 0; c < CD; c++) mu += z[c];
    mu *= (1.0f / CD);
    float var = 0.f;
#pragma unroll
    for (int c = 0; c < CD; c++) { float t = z[c] - mu; var = fmaf(t, t, var); }
    var *= (1.0f / CD);
    float inv = rsqrtf(var + 1e-5f);

    float* o = g_z + (size_t)(tokBase + tid) * CD;
#pragma unroll
    for (int c = 0; c < CD; c++) o[c] = (z[c] - mu) * inv;
}

// ---------------- kernel 2: mma.sync scan + fused argmax ----------------------
// 128 CTAs x 512 thr (16 warps, 2x8: M-half x N-eighth). A (z fp16 2-split)
// register-resident; codebook image streamed via cp.async double-buffering.
// Bias folded into the MMA accumulator initialization.
__global__ void __launch_bounds__(SCAN_THREADS)
scan_mma_kernel(float* __restrict__ out) {
    extern __shared__ __align__(16) unsigned char sm[];
    const uint32_t sb = smem_u32(sm);

    const int tid  = threadIdx.x;
    const int lane = tid & 31;
    const int w    = tid >> 5;
    const int g    = lane >> 2;      // group id (0..7)
    const int t    = lane & 3;       // thread-in-group
    const int mi   = w >> 3;         // M half (0..1)
    const int nj   = w & 7;          // N eighth (0..7)
    const int m_base = mi * 64;
    const int njOff  = nj * 16;
    const int ctaTok = blockIdx.x * 128;

    unsigned long long* res = reinterpret_cast<unsigned long long*>(sm + OFF_RES);
    if (tid < 128) res[tid] = 0ull;

    // stage z for this CTA's 128 tokens (8KB, coalesced)
    {
        const float4* src = reinterpret_cast<const float4*>(g_z + (size_t)ctaTok * CD);
        float4* dst = reinterpret_cast<float4*>(sm + OFF_Z);
        dst[tid] = src[tid];
    }
    __syncthreads();

    // ---- build register-resident A fragments: afr[mt][kb][0..3] ----
    uint32_t afr[4][KB][4];
    {
        const float* zb = reinterpret_cast<const float*>(sm + OFF_Z);
        unsigned short sp[2][8][4];   // [level][slot s: row=m_base+g+8s][col j0..j3]
#pragma unroll
        for (int s = 0; s < 8; s++) {
            int row = m_base + g + 8 * s;
#pragma unroll
            for (int jj = 0; jj < 4; jj++) {
                int col = 2 * t + ((jj & 2) ? 8 : 0) + (jj & 1);
                unsigned short h, m;
                split2(zb[row * CD + col], h, m);
                sp[0][s][jj] = h; sp[1][s][jj] = m;
            }
        }
#pragma unroll
        for (int mt = 0; mt < 4; mt++) {
#pragma unroll
            for (int kb = 0; kb < KB; kb++) {
                int lv = lvlA(kb);
                int s0 = 2 * mt, s1 = 2 * mt + 1;
                afr[mt][kb][0] = (uint32_t)sp[lv][s0][0] | ((uint32_t)sp[lv][s0][1] << 16);
                afr[mt][kb][1] = (uint32_t)sp[lv][s1][0] | ((uint32_t)sp[lv][s1][1] << 16);
                afr[mt][kb][2] = (uint32_t)sp[lv][s0][2] | ((uint32_t)sp[lv][s0][3] << 16);
                afr[mt][kb][3] = (uint32_t)sp[lv][s1][2] | ((uint32_t)sp[lv][s1][3] << 16);
            }
        }
    }

    // ---- cp.async staging ----
    auto stage = [&](int ch, int buf) {
        const unsigned char* src = g_img + (size_t)ch * CHUNK_B;
        uint32_t dstB = sb + (buf ? OFF_B1 : OFF_B0);
        for (int idx = tid; idx < CHUNK_B / 16; idx += SCAN_THREADS)
            cpa16(dstB + idx * 16, src + idx * 16);
        if (tid < 32)
            cpa16(sb + (buf ? OFF_HB1 : OFF_HB0) + tid * 16,
                  g_hbneg + ch * CHUNK_N + tid * 4);
    };

    stage(0, 0);
    cpa_commit();

    float best[8];
    int   bidx[8];
#pragma unroll
    for (int s = 0; s < 8; s++) { best[s] = -3.0e38f; bidx[s] = 0; }

    for (int ch = 0; ch < NCHUNK; ch++) {
        const int buf = ch & 1;
        if (ch + 1 < NCHUNK) {
            stage(ch + 1, buf ^ 1);
            cpa_commit();
            cpa_wait1();
        } else {
            cpa_wait0();
        }
        __syncthreads();   // chunk ch data visible to all warps

        const uint32_t bB = sb + (buf ? OFF_B1 : OFF_B0);
        const float* hbs = reinterpret_cast<const float*>(
            sm + (buf ? OFF_HB1 : OFF_HB0));
        const int cbase = ch * CHUNK_N + njOff;

#pragma unroll
        for (int nt = 0; nt < 2; nt++) {
            const int ncol = njOff + nt * 8 + g;      // B column for this thread
            // bias (per code column) folded into accumulator init
            const float bx = hbs[njOff + nt * 8 + 2 * t];
            const float by = hbs[njOff + nt * 8 + 2 * t + 1];
            float d0[4], d1[4], d2[4], d3[4];
#pragma unroll
            for (int mt = 0; mt < 4; mt++) { d0[mt]=bx; d1[mt]=by; d2[mt]=bx; d3[mt]=by; }

#pragma unroll
            for (int kb = 0; kb < KB; kb++) {
                uint32_t b0, b1;
                uint32_t addr = bB + ncol * ROWB + kb * 32 + t * 8;
                asm volatile("ld.shared.v2.u32 {%0,%1}, [%2];"
                             : "=r"(b0), "=r"(b1) : "r"(addr));
#pragma unroll
                for (int mt = 0; mt < 4; mt++) {
                    float dd[4] = {d0[mt], d1[mt], d2[mt], d3[mt]};
                    mma16816(dd, afr[mt][kb], b0, b1);
                    d0[mt]=dd[0]; d1[mt]=dd[1]; d2[mt]=dd[2]; d3[mt]=dd[3];
                }
            }

            // epilogue: running argmax (ascending col order, strict >)
            const int c0 = cbase + nt * 8 + 2 * t;
#pragma unroll
            for (int mt = 0; mt < 4; mt++) {
                int se = 2 * mt, so = 2 * mt + 1;
                if (d0[mt] > best[se]) { best[se] = d0[mt]; bidx[se] = c0; }
                if (d1[mt] > best[se]) { best[se] = d1[mt]; bidx[se] = c0 + 1; }
                if (d2[mt] > best[so]) { best[so] = d2[mt]; bidx[so] = c0; }
                if (d3[mt] > best[so]) { best[so] = d3[mt]; bidx[so] = c0 + 1; }
            }
        }
        __syncthreads();   // all warps done with buf before it is overwritten
    }

    // ---- combine: quad shfl-reduce, then packed-key max across warps ----
#pragma unroll
    for (int s = 0; s < 8; s++) {
        unsigned int kh = ordf(best[s]);
        unsigned int kl = (unsigned int)(CS - 1 - bidx[s]);
#pragma unroll
        for (int o = 1; o < 4; o <<= 1) {
            unsigned int oh = __shfl_xor_sync(0xffffffffu, kh, o);
            unsigned int ol = __shfl_xor_sync(0xffffffffu, kl, o);
            if (oh > kh || (oh == kh && ol > kl)) { kh = oh; kl = ol; }
        }
        if (t == 0) {
            unsigned long long key = ((unsigned long long)kh << 32) | kl;
            atomicMax(&res[m_base + g + 8 * s], key);
        }
    }
    __syncthreads();

    if (tid < 128) {
        unsigned int low = (unsigned int)(res[tid] & 0xffffffffu);
        out[ctaTok + tid] = (float)(CS - 1 - (int)low);
    }
}

// ---------------- launch ----------------
extern "C" void kernel_launch(void* const* d_in, const int* in_sizes, int n_in,
                              void* d_out, int out_size) {
    const float* x  = nullptr;
    const float* W  = nullptr;
    const float* cb = nullptr;
    for (int i = 0; i < n_in; i++) {
        if      (in_sizes[i] == N_X)      x  = (const float*)d_in[i];
        else if (in_sizes[i] == N_W)      W  = (const float*)d_in[i];
        else if (in_sizes[i] == N_CB)     cb = (const float*)d_in[i];
        else if (in_sizes[i] == 4 * N_X)  x  = (const float*)d_in[i];
        else if (in_sizes[i] == 4 * N_W)  W  = (const float*)d_in[i];
        else if (in_sizes[i] == 4 * N_CB) cb = (const float*)d_in[i];
    }
    if (!x)  x  = (const float*)d_in[0];
    if (!W)  W  = (const float*)d_in[1];
    if (!cb) cb = (const float*)d_in[2];

    float* out = (float*)d_out;   // (8,2048) float32 codes

    cudaFuncSetAttribute(scan_mma_kernel,
                         cudaFuncAttributeMaxDynamicSharedMemorySize, SCAN_SMEM);

    prep_kernel<<<CS / 256, 256>>>(cb);
    prep_image_kernel<<<(CS * 4) / 256, 256>>>(cb);
    proj_ln_kernel<<<TOKENS / P1_BLOCK, P1_BLOCK>>>(x, W);
    scan_mma_kernel<<<TOKENS / 128, SCAN_THREADS, SCAN_SMEM>>>(out);
}

// round 12
// speedup vs baseline: 1.1099x; 1.1099x over previous
#include <cuda_runtime.h>
#include <cuda_fp16.h>
#include <cstdint>

// Problem constants (fixed by setup_inputs)
#define TOKENS 16384
#define DIM    1024
#define CD     16
#define CS     8192

#define N_X  (TOKENS * DIM)
#define N_W  (CD * DIM)
#define N_CB (CS * CD)

// ---- scan tiling ----
#define CHUNK_N   128                 // codes per chunk
#define NCHUNK    (CS / CHUNK_N)      // 64
#define ROWB      112                 // bytes/code row: 56 halves (48 data + 8 pad)
#define SCAN_THREADS 512
#define KB        3                   // fp16 2-split products: hh,hm,mh
#define WSLICE    16                  // columns per warp
#define WSLICE_B  (WSLICE * ROWB)     // 1792 B per warp per chunk
#define WAREA     (2 * WSLICE_B + 2 * 64)   // 3712 B per warp (2 B bufs + 2 hb bufs)

// scan smem layout
#define OFF_Z    (16 * WAREA)                // 59392
#define OFF_RES  (OFF_Z + 128 * CD * 4)      // +8192
#define SCAN_SMEM (OFF_RES + 128 * 8)        // +1024 = 68608

// proj config
#define P1_THREADS 256
#define P1_TPB     64                        // tokens per block (4 thr/token)
#define P1_QS      4100                      // quarter stride in floats (256*16+4 pad)
#define P1_SMEM    (4 * P1_QS * 4)           // 65600 B

__device__ __align__(16) float g_z[TOKENS * CD];
__device__ float g_hbneg[CS];                               // -0.5*||c||^2
__device__ __align__(16) unsigned char g_img[CS * ROWB];    // 896KB split-codebook image

// ---------------- helpers ----------------
__device__ __forceinline__ uint32_t smem_u32(const void* p) {
    uint32_t a;
    asm("{ .reg .u64 t; cvta.to.shared.u64 t, %1; cvt.u32.u64 %0, t; }"
        : "=r"(a) : "l"(p));
    return a;
}
__device__ __forceinline__ void cpa16(uint32_t dst, const void* src) {
    asm volatile("cp.async.ca.shared.global [%0], [%1], 16;"
                 :: "r"(dst), "l"(src) : "memory");
}
__device__ __forceinline__ void cpa_commit() {
    asm volatile("cp.async.commit_group;" ::: "memory");
}
__device__ __forceinline__ void cpa_wait1() {
    asm volatile("cp.async.wait_group 1;" ::: "memory");
}
__device__ __forceinline__ void cpa_wait0() {
    asm volatile("cp.async.wait_group 0;" ::: "memory");
}
__device__ __forceinline__ unsigned int ordf(float f) {
    unsigned int u = __float_as_uint(f);
    return (u & 0x80000000u) ? ~u : (u | 0x80000000u);
}
__device__ __forceinline__ void split2(float f, unsigned short& h, unsigned short& m) {
    __half hh = __float2half_rn(f);
    float fh = __half2float(hh);
    __half mm = __float2half_rn(f - fh);
    h = *reinterpret_cast<unsigned short*>(&hh);
    m = *reinterpret_cast<unsigned short*>(&mm);
}
__device__ __forceinline__ int lvlA(int kb) { return kb >> 1; }
__device__ __forceinline__ int lvlB(int kb) { return kb & 1; }

__device__ __forceinline__ void mma16816(float* d, const uint32_t* a,
                                         uint32_t b0, uint32_t b1) {
    asm volatile(
        "mma.sync.aligned.m16n8k16.row.col.f32.f16.f16.f32 "
        "{%0,%1,%2,%3},{%4,%5,%6,%7},{%8,%9},{%0,%1,%2,%3};"
        : "+f"(d[0]), "+f"(d[1]), "+f"(d[2]), "+f"(d[3])
        : "r"(a[0]), "r"(a[1]), "r"(a[2]), "r"(a[3]), "r"(b0), "r"(b1));
}

// ---------------- kernel 0a: -0.5*||c||^2 ----------------
__global__ void prep_kernel(const float* __restrict__ cb) {
    int k = blockIdx.x * blockDim.x + threadIdx.x;
    if (k < CS) {
        float s = 0.f;
#pragma unroll
        for (int i = 0; i < CD; i++) {
            float v = cb[(size_t)k * CD + i];
            s = fmaf(v, v, s);
        }
        g_hbneg[k] = -0.5f * s;
    }
}

// ---------------- kernel 0b: split codebook -> B-fragment image ----------------
__global__ void prep_image_kernel(const float* __restrict__ cb) {
    int idx = blockIdx.x * blockDim.x + threadIdx.x;
    if (idx >= CS * 4) return;
    int k = idx >> 2;
    int t = idx & 3;
    const float* row = cb + (size_t)k * CD;
    float c0 = row[2 * t],     c1 = row[2 * t + 1];
    float c8 = row[2 * t + 8], c9 = row[2 * t + 9];
    unsigned short h0, m0, h1, m1, h8, m8, h9, m9;
    split2(c0, h0, m0); split2(c1, h1, m1);
    split2(c8, h8, m8); split2(c9, h9, m9);
    uint32_t wh0 = (uint32_t)h0 | ((uint32_t)h1 << 16);
    uint32_t wh1 = (uint32_t)h8 | ((uint32_t)h9 << 16);
    uint32_t wm0 = (uint32_t)m0 | ((uint32_t)m1 << 16);
    uint32_t wm1 = (uint32_t)m8 | ((uint32_t)m9 << 16);
    uint32_t* base = reinterpret_cast<uint32_t*>(g_img + (size_t)k * ROWB);
#pragma unroll
    for (int kb = 0; kb < KB; kb++) {
        uint32_t* p = base + kb * 8 + t * 2;
        if (lvlB(kb)) { p[0] = wm0; p[1] = wm1; }
        else          { p[0] = wh0; p[1] = wh1; }
    }
    if (t == 0) {
        uint4 zz = {0u, 0u, 0u, 0u};
        *reinterpret_cast<uint4*>(base + 24) = zz;
    }
}

// ---------------- kernel 1: projection + LayerNorm (4 threads / token) ---------
// Block 256 thr = 64 tokens x 4 D-quarters. W fully staged transposed into
// padded smem (quarter stride 4100 floats -> conflict-free broadcast LDS.128).
// x streamed per-lane contiguous; quad shfl-combine; leader does LN + store.
__global__ void __launch_bounds__(P1_THREADS)
proj_ln_kernel(const float* __restrict__ x, const float* __restrict__ W) {
    extern __shared__ __align__(16) float wt[];   // 4 * 4100 floats

    const int tid = threadIdx.x;
    const int t4  = tid & 3;          // D quarter
    const int row = tid >> 2;         // token within block
    const int token = blockIdx.x * P1_TPB + row;

    // stage W transposed: wt[dq*QS + dloc*16 + c] = W[c*DIM + d]
    for (int i = 0; i < N_W / P1_THREADS; i++) {
        int idx = tid + i * P1_THREADS;
        int c = idx >> 10, d = idx & 1023;
        wt[(d >> 8) * P1_QS + (d & 255) * 16 + c] = W[idx];
    }
    __syncthreads();

    float acc[CD];
#pragma unroll
    for (int c = 0; c < CD; c++) acc[c] = 0.f;

    const float* xrow = x + (size_t)token * DIM + t4 * 256;
    const float* wq = wt + t4 * P1_QS;

    for (int db = 0; db < 256; db += 4) {
        float4 xv = *reinterpret_cast<const float4*>(xrow + db);
        const float* w0 = wq + (db + 0) * 16;
        const float* w1 = wq + (db + 1) * 16;
        const float* w2 = wq + (db + 2) * 16;
        const float* w3 = wq + (db + 3) * 16;
#pragma unroll
        for (int c = 0; c < CD; c++) {
            acc[c] = fmaf(xv.x, w0[c], acc[c]);
            acc[c] = fmaf(xv.y, w1[c], acc[c]);
            acc[c] = fmaf(xv.z, w2[c], acc[c]);
            acc[c] = fmaf(xv.w, w3[c], acc[c]);
        }
    }

    // combine 4 quarters within the quad
#pragma unroll
    for (int c = 0; c < CD; c++) {
        acc[c] += __shfl_xor_sync(0xffffffffu, acc[c], 1);
        acc[c] += __shfl_xor_sync(0xffffffffu, acc[c], 2);
    }

    if (t4 == 0) {
        float mu = 0.f;
#pragma unroll
        for (int c = 0; c < CD; c++) mu += acc[c];
        mu *= (1.0f / CD);
        float var = 0.f;
#pragma unroll
        for (int c = 0; c < CD; c++) { float d = acc[c] - mu; var = fmaf(d, d, var); }
        var *= (1.0f / CD);
        float inv = rsqrtf(var + 1e-5f);
        float* o = g_z + (size_t)token * CD;
#pragma unroll
        for (int c = 0; c < CD; c++) o[c] = (acc[c] - mu) * inv;
    }
}

// ---------------- kernel 2: warp-independent mma.sync scan --------------------
// 128 CTAs x 512 thr (16 warps, 2x8: M-half x N-eighth). Each warp stages its
// OWN 16-column slice per chunk (cp.async, per-warp double buffer) -> zero
// block barriers in the mainloop.
__global__ void __launch_bounds__(SCAN_THREADS)
scan_mma_kernel(float* __restrict__ out) {
    extern __shared__ __align__(16) unsigned char sm[];
    const uint32_t sb = smem_u32(sm);

    const int tid  = threadIdx.x;
    const int lane = tid & 31;
    const int w    = tid >> 5;
    const int g    = lane >> 2;
    const int t    = lane & 3;
    const int mi   = w >> 3;          // M half
    const int nj   = w & 7;           // N eighth
    const int m_base = mi * 64;
    const int njOff  = nj * WSLICE;   // global column offset of this warp's slice
    const int ctaTok = blockIdx.x * 128;
    const uint32_t wbase = sb + w * WAREA;

    unsigned long long* res = reinterpret_cast<unsigned long long*>(sm + OFF_RES);
    if (tid < 128) res[tid] = 0ull;

    // stage z (8KB, coalesced)
    {
        const float4* src = reinterpret_cast<const float4*>(g_z + (size_t)ctaTok * CD);
        float4* dst = reinterpret_cast<float4*>(sm + OFF_Z);
        dst[tid] = src[tid];
    }
    __syncthreads();

    // ---- register-resident A fragments ----
    uint32_t afr[4][KB][4];
    {
        const float* zb = reinterpret_cast<const float*>(sm + OFF_Z);
        unsigned short sp[2][8][4];
#pragma unroll
        for (int s = 0; s < 8; s++) {
            int row = m_base + g + 8 * s;
#pragma unroll
            for (int jj = 0; jj < 4; jj++) {
                int col = 2 * t + ((jj & 2) ? 8 : 0) + (jj & 1);
                unsigned short h, m;
                split2(zb[row * CD + col], h, m);
                sp[0][s][jj] = h; sp[1][s][jj] = m;
            }
        }
#pragma unroll
        for (int mt = 0; mt < 4; mt++) {
#pragma unroll
            for (int kb = 0; kb < KB; kb++) {
                int lv = lvlA(kb);
                int s0 = 2 * mt, s1 = 2 * mt + 1;
                afr[mt][kb][0] = (uint32_t)sp[lv][s0][0] | ((uint32_t)sp[lv][s0][1] << 16);
                afr[mt][kb][1] = (uint32_t)sp[lv][s1][0] | ((uint32_t)sp[lv][s1][1] << 16);
                afr[mt][kb][2] = (uint32_t)sp[lv][s0][2] | ((uint32_t)sp[lv][s0][3] << 16);
                afr[mt][kb][3] = (uint32_t)sp[lv][s1][2] | ((uint32_t)sp[lv][s1][3] << 16);
            }
        }
    }

    // ---- per-warp staging: 16 columns x 112B = 1792B + 64B biases ----
    auto stage = [&](int ch, int buf) {
        const unsigned char* src = g_img + (size_t)(ch * CHUNK_N + njOff) * ROWB;
        uint32_t dstB = wbase + buf * WSLICE_B;
        // 112 x 16B transfers across 32 lanes
        cpa16(dstB + lane * 16,        src + lane * 16);
        cpa16(dstB + (lane + 32) * 16, src + (lane + 32) * 16);
        cpa16(dstB + (lane + 64) * 16, src + (lane + 64) * 16);
        if (lane < 16) cpa16(dstB + (lane + 96) * 16, src + (lane + 96) * 16);
        // 16 bias floats = 4 x 16B
        if (lane < 4)
            cpa16(wbase + 2 * WSLICE_B + buf * 64 + lane * 16,
                  g_hbneg + ch * CHUNK_N + njOff + lane * 4);
        cpa_commit();
    };

    stage(0, 0);
    stage(1, 1);

    float best[8];
    int   bidx[8];
#pragma unroll
    for (int s = 0; s < 8; s++) { best[s] = -3.0e38f; bidx[s] = 0; }

    for (int ch = 0; ch < NCHUNK; ch++) {
        const int buf = ch & 1;
        if (ch < NCHUNK - 1) cpa_wait1(); else cpa_wait0();
        __syncwarp();

        const uint32_t bB = wbase + buf * WSLICE_B;
        const float* hbs = reinterpret_cast<const float*>(
            sm + (wbase - sb) + 2 * WSLICE_B + buf * 64);
        const int cbase = ch * CHUNK_N + njOff;

#pragma unroll
        for (int nt = 0; nt < 2; nt++) {
            const int lcol = nt * 8 + g;        // local column in slice
            const float bx = hbs[nt * 8 + 2 * t];
            const float by = hbs[nt * 8 + 2 * t + 1];
            float d0[4], d1[4], d2[4], d3[4];
#pragma unroll
            for (int mt = 0; mt < 4; mt++) { d0[mt]=bx; d1[mt]=by; d2[mt]=bx; d3[mt]=by; }

#pragma unroll
            for (int kb = 0; kb < KB; kb++) {
                uint32_t b0, b1;
                uint32_t addr = bB + lcol * ROWB + kb * 32 + t * 8;
                asm volatile("ld.shared.v2.u32 {%0,%1}, [%2];"
                             : "=r"(b0), "=r"(b1) : "r"(addr));
#pragma unroll
                for (int mt = 0; mt < 4; mt++) {
                    float dd[4] = {d0[mt], d1[mt], d2[mt], d3[mt]};
                    mma16816(dd, afr[mt][kb], b0, b1);
                    d0[mt]=dd[0]; d1[mt]=dd[1]; d2[mt]=dd[2]; d3[mt]=dd[3];
                }
            }

            const int c0 = cbase + nt * 8 + 2 * t;
#pragma unroll
            for (int mt = 0; mt < 4; mt++) {
                int se = 2 * mt, so = 2 * mt + 1;
                if (d0[mt] > best[se]) { best[se] = d0[mt]; bidx[se] = c0; }
                if (d1[mt] > best[se]) { best[se] = d1[mt]; bidx[se] = c0 + 1; }
                if (d2[mt] > best[so]) { best[so] = d2[mt]; bidx[so] = c0; }
                if (d3[mt] > best[so]) { best[so] = d3[mt]; bidx[so] = c0 + 1; }
            }
        }

        if (ch + 2 < NCHUNK) stage(ch + 2, buf);   // overwrite just-computed buf
    }

    // ---- combine: quad shfl-reduce, then packed-key max across warps ----
#pragma unroll
    for (int s = 0; s < 8; s++) {
        unsigned int kh = ordf(best[s]);
        unsigned int kl = (unsigned int)(CS - 1 - bidx[s]);
#pragma unroll
        for (int o = 1; o < 4; o <<= 1) {
            unsigned int oh = __shfl_xor_sync(0xffffffffu, kh, o);
            unsigned int ol = __shfl_xor_sync(0xffffffffu, kl, o);
            if (oh > kh || (oh == kh && ol > kl)) { kh = oh; kl = ol; }
        }
        if (t == 0) {
            unsigned long long key = ((unsigned long long)kh << 32) | kl;
            atomicMax(&res[m_base + g + 8 * s], key);
        }
    }
    __syncthreads();

    if (tid < 128) {
        unsigned int low = (unsigned int)(res[tid] & 0xffffffffu);
        out[ctaTok + tid] = (float)(CS - 1 - (int)low);
    }
}

// ---------------- launch ----------------
extern "C" void kernel_launch(void* const* d_in, const int* in_sizes, int n_in,
                              void* d_out, int out_size) {
    const float* x  = nullptr;
    const float* W  = nullptr;
    const float* cb = nullptr;
    for (int i = 0; i < n_in; i++) {
        if      (in_sizes[i] == N_X)      x  = (const float*)d_in[i];
        else if (in_sizes[i] == N_W)      W  = (const float*)d_in[i];
        else if (in_sizes[i] == N_CB)     cb = (const float*)d_in[i];
        else if (in_sizes[i] == 4 * N_X)  x  = (const float*)d_in[i];
        else if (in_sizes[i] == 4 * N_W)  W  = (const float*)d_in[i];
        else if (in_sizes[i] == 4 * N_CB) cb = (const float*)d_in[i];
    }
    if (!x)  x  = (const float*)d_in[0];
    if (!W)  W  = (const float*)d_in[1];
    if (!cb) cb = (const float*)d_in[2];

    float* out = (float*)d_out;   // (8,2048) float32 codes

    cudaFuncSetAttribute(scan_mma_kernel,
                         cudaFuncAttributeMaxDynamicSharedMemorySize, SCAN_SMEM);
    cudaFuncSetAttribute(proj_ln_kernel,
                         cudaFuncAttributeMaxDynamicSharedMemorySize, P1_SMEM);

    prep_kernel<<<CS / 256, 256>>>(cb);
    prep_image_kernel<<<(CS * 4) / 256, 256>>>(cb);
    proj_ln_kernel<<<TOKENS / P1_TPB, P1_THREADS, P1_SMEM>>>(x, W);
    scan_mma_kernel<<<TOKENS / 128, SCAN_THREADS, SCAN_SMEM>>>(out);
}

// round 13
// speedup vs baseline: 1.1363x; 1.0238x over previous
#include <cuda_runtime.h>
#include <cuda_fp16.h>
#include <cstdint>

// Problem constants (fixed by setup_inputs)
#define TOKENS 16384
#define DIM    1024
#define CD     16
#define CS     8192

#define N_X  (TOKENS * DIM)
#define N_W  (CD * DIM)
#define N_CB (CS * CD)

// ---- scan tiling ----
#define CHUNK_N   128
#define NCHUNK    (CS / CHUNK_N)      // 64
#define ROWB      112                 // bytes/code row: 56 halves (48 data + 8 pad)
#define SCAN_THREADS 512
#define KB        3                   // fp16 2-split products: hh,hm,mh
#define WSLICE    16                  // columns per warp
#define WSLICE_B  (WSLICE * ROWB)     // 1792 B
#define WAREA     (2 * WSLICE_B + 2 * 64)

#define OFF_Z    (16 * WAREA)
#define OFF_RES  (OFF_Z + 128 * CD * 4)
#define SCAN_SMEM (OFF_RES + 128 * 8)

// proj config (fused kernel, blocks [0,256))
#define P1_THREADS 256
#define P1_TPB     64
#define P1_QS      4100
#define P1_SMEM    (4 * P1_QS * 4)    // 65600 B

#define NB_PROJ  (TOKENS / P1_TPB)          // 256
#define NB_IMG   (CS * 4 / 256)             // 128
#define NB_PREP  (CS / 256)                 // 32
#define NB_FUSED (NB_PROJ + NB_IMG + NB_PREP)

__device__ __align__(16) float g_z[TOKENS * CD];
__device__ float g_hbneg[CS];
__device__ __align__(16) unsigned char g_img[CS * ROWB];

// ---------------- helpers ----------------
__device__ __forceinline__ uint32_t smem_u32(const void* p) {
    uint32_t a;
    asm("{ .reg .u64 t; cvta.to.shared.u64 t, %1; cvt.u32.u64 %0, t; }"
        : "=r"(a) : "l"(p));
    return a;
}
__device__ __forceinline__ void cpa16(uint32_t dst, const void* src) {
    asm volatile("cp.async.ca.shared.global [%0], [%1], 16;"
                 :: "r"(dst), "l"(src) : "memory");
}
__device__ __forceinline__ void cpa_commit() {
    asm volatile("cp.async.commit_group;" ::: "memory");
}
__device__ __forceinline__ void cpa_wait1() {
    asm volatile("cp.async.wait_group 1;" ::: "memory");
}
__device__ __forceinline__ void cpa_wait0() {
    asm volatile("cp.async.wait_group 0;" ::: "memory");
}
__device__ __forceinline__ unsigned int ordf(float f) {
    unsigned int u = __float_as_uint(f);
    return (u & 0x80000000u) ? ~u : (u | 0x80000000u);
}
__device__ __forceinline__ void split2(float f, unsigned short& h, unsigned short& m) {
    __half hh = __float2half_rn(f);
    float fh = __half2float(hh);
    __half mm = __float2half_rn(f - fh);
    h = *reinterpret_cast<unsigned short*>(&hh);
    m = *reinterpret_cast<unsigned short*>(&mm);
}
__device__ __forceinline__ int lvlA(int kb) { return kb >> 1; }
__device__ __forceinline__ int lvlB(int kb) { return kb & 1; }

__device__ __forceinline__ void mma16816(float* d, const uint32_t* a,
                                         uint32_t b0, uint32_t b1) {
    asm volatile(
        "mma.sync.aligned.m16n8k16.row.col.f32.f16.f16.f32 "
        "{%0,%1,%2,%3},{%4,%5,%6,%7},{%8,%9},{%0,%1,%2,%3};"
        : "+f"(d[0]), "+f"(d[1]), "+f"(d[2]), "+f"(d[3])
        : "r"(a[0]), "r"(a[1]), "r"(a[2]), "r"(a[3]), "r"(b0), "r"(b1));
}

// ---------------- fused kernel: proj+LN | codebook image | bias ----------------
__global__ void __launch_bounds__(P1_THREADS)
fused_prep_kernel(const float* __restrict__ x, const float* __restrict__ W,
                  const float* __restrict__ cb) {
    const int b = blockIdx.x;
    const int tid = threadIdx.x;

    if (b < NB_PROJ) {
        // ---- projection + LayerNorm: 64 tokens x 4 D-quarters ----
        extern __shared__ __align__(16) float wt[];
        const int t4  = tid & 3;
        const int row = tid >> 2;
        const int token = b * P1_TPB + row;

        for (int i = 0; i < N_W / P1_THREADS; i++) {
            int idx = tid + i * P1_THREADS;
            int c = idx >> 10, d = idx & 1023;
            wt[(d >> 8) * P1_QS + (d & 255) * 16 + c] = W[idx];
        }
        __syncthreads();

        float acc[CD];
#pragma unroll
        for (int c = 0; c < CD; c++) acc[c] = 0.f;

        const float* xrow = x + (size_t)token * DIM + t4 * 256;
        const float* wq = wt + t4 * P1_QS;

        for (int db = 0; db < 256; db += 4) {
            float4 xv = *reinterpret_cast<const float4*>(xrow + db);
            const float* w0 = wq + (db + 0) * 16;
            const float* w1 = wq + (db + 1) * 16;
            const float* w2 = wq + (db + 2) * 16;
            const float* w3 = wq + (db + 3) * 16;
#pragma unroll
            for (int c = 0; c < CD; c++) {
                acc[c] = fmaf(xv.x, w0[c], acc[c]);
                acc[c] = fmaf(xv.y, w1[c], acc[c]);
                acc[c] = fmaf(xv.z, w2[c], acc[c]);
                acc[c] = fmaf(xv.w, w3[c], acc[c]);
            }
        }
#pragma unroll
        for (int c = 0; c < CD; c++) {
            acc[c] += __shfl_xor_sync(0xffffffffu, acc[c], 1);
            acc[c] += __shfl_xor_sync(0xffffffffu, acc[c], 2);
        }
        if (t4 == 0) {
            float mu = 0.f;
#pragma unroll
            for (int c = 0; c < CD; c++) mu += acc[c];
            mu *= (1.0f / CD);
            float var = 0.f;
#pragma unroll
            for (int c = 0; c < CD; c++) { float d = acc[c] - mu; var = fmaf(d, d, var); }
            var *= (1.0f / CD);
            float inv = rsqrtf(var + 1e-5f);
            float* o = g_z + (size_t)token * CD;
#pragma unroll
            for (int c = 0; c < CD; c++) o[c] = (acc[c] - mu) * inv;
        }
    } else if (b < NB_PROJ + NB_IMG) {
        // ---- split codebook -> B-fragment image ----
        int idx = (b - NB_PROJ) * 256 + tid;        // 0 .. CS*4-1
        int k = idx >> 2;
        int t = idx & 3;
        const float* row = cb + (size_t)k * CD;
        float c0 = row[2 * t],     c1 = row[2 * t + 1];
        float c8 = row[2 * t + 8], c9 = row[2 * t + 9];
        unsigned short h0, m0, h1, m1, h8, m8, h9, m9;
        split2(c0, h0, m0); split2(c1, h1, m1);
        split2(c8, h8, m8); split2(c9, h9, m9);
        uint32_t wh0 = (uint32_t)h0 | ((uint32_t)h1 << 16);
        uint32_t wh1 = (uint32_t)h8 | ((uint32_t)h9 << 16);
        uint32_t wm0 = (uint32_t)m0 | ((uint32_t)m1 << 16);
        uint32_t wm1 = (uint32_t)m8 | ((uint32_t)m9 << 16);
        uint32_t* base = reinterpret_cast<uint32_t*>(g_img + (size_t)k * ROWB);
#pragma unroll
        for (int kb = 0; kb < KB; kb++) {
            uint32_t* p = base + kb * 8 + t * 2;
            if (lvlB(kb)) { p[0] = wm0; p[1] = wm1; }
            else          { p[0] = wh0; p[1] = wh1; }
        }
        if (t == 0) {
            uint4 zz = {0u, 0u, 0u, 0u};
            *reinterpret_cast<uint4*>(base + 24) = zz;
        }
    } else {
        // ---- -0.5*||c||^2 ----
        int k = (b - NB_PROJ - NB_IMG) * 256 + tid;
        float s = 0.f;
#pragma unroll
        for (int i = 0; i < CD; i++) {
            float v = cb[(size_t)k * CD + i];
            s = fmaf(v, v, s);
        }
        g_hbneg[k] = -0.5f * s;
    }
}

// ---------------- scan: warp-independent mma.sync + fused argmax ---------------
__global__ void __launch_bounds__(SCAN_THREADS)
scan_mma_kernel(float* __restrict__ out) {
    extern __shared__ __align__(16) unsigned char sm[];
    const uint32_t sb = smem_u32(sm);

    const int tid  = threadIdx.x;
    const int lane = tid & 31;
    const int w    = tid >> 5;
    const int g    = lane >> 2;
    const int t    = lane & 3;
    const int mi   = w >> 3;
    const int nj   = w & 7;
    const int m_base = mi * 64;
    const int njOff  = nj * WSLICE;
    const int ctaTok = blockIdx.x * 128;
    const uint32_t wbase = sb + w * WAREA;

    unsigned long long* res = reinterpret_cast<unsigned long long*>(sm + OFF_RES);
    if (tid < 128) res[tid] = 0ull;

    {
        const float4* src = reinterpret_cast<const float4*>(g_z + (size_t)ctaTok * CD);
        float4* dst = reinterpret_cast<float4*>(sm + OFF_Z);
        dst[tid] = src[tid];
    }
    __syncthreads();

    // ---- register-resident A fragments ----
    uint32_t afr[4][KB][4];
    {
        const float* zb = reinterpret_cast<const float*>(sm + OFF_Z);
        unsigned short sp[2][8][4];
#pragma unroll
        for (int s = 0; s < 8; s++) {
            int row = m_base + g + 8 * s;
#pragma unroll
            for (int jj = 0; jj < 4; jj++) {
                int col = 2 * t + ((jj & 2) ? 8 : 0) + (jj & 1);
                unsigned short h, m;
                split2(zb[row * CD + col], h, m);
                sp[0][s][jj] = h; sp[1][s][jj] = m;
            }
        }
#pragma unroll
        for (int mt = 0; mt < 4; mt++) {
#pragma unroll
            for (int kb = 0; kb < KB; kb++) {
                int lv = lvlA(kb);
                int s0 = 2 * mt, s1 = 2 * mt + 1;
                afr[mt][kb][0] = (uint32_t)sp[lv][s0][0] | ((uint32_t)sp[lv][s0][1] << 16);
                afr[mt][kb][1] = (uint32_t)sp[lv][s1][0] | ((uint32_t)sp[lv][s1][1] << 16);
                afr[mt][kb][2] = (uint32_t)sp[lv][s0][2] | ((uint32_t)sp[lv][s0][3] << 16);
                afr[mt][kb][3] = (uint32_t)sp[lv][s1][2] | ((uint32_t)sp[lv][s1][3] << 16);
            }
        }
    }

    // ---- per-warp staging ----
    auto stage = [&](int ch, int buf) {
        const unsigned char* src = g_img + (size_t)(ch * CHUNK_N + njOff) * ROWB;
        uint32_t dstB = wbase + buf * WSLICE_B;
        cpa16(dstB + lane * 16,        src + lane * 16);
        cpa16(dstB + (lane + 32) * 16, src + (lane + 32) * 16);
        cpa16(dstB + (lane + 64) * 16, src + (lane + 64) * 16);
        if (lane < 16) cpa16(dstB + (lane + 96) * 16, src + (lane + 96) * 16);
        if (lane < 4)
            cpa16(wbase + 2 * WSLICE_B + buf * 64 + lane * 16,
                  g_hbneg + ch * CHUNK_N + njOff + lane * 4);
        cpa_commit();
    };

    stage(0, 0);
    stage(1, 1);

    float best[8];
    int   bidx[8];
#pragma unroll
    for (int s = 0; s < 8; s++) { best[s] = -3.0e38f; bidx[s] = 0; }

    for (int ch = 0; ch < NCHUNK; ch++) {
        const int buf = ch & 1;
        if (ch < NCHUNK - 1) cpa_wait1(); else cpa_wait0();
        __syncwarp();

        const uint32_t bB = wbase + buf * WSLICE_B;
        const float* hbs = reinterpret_cast<const float*>(
            sm + (wbase - sb) + 2 * WSLICE_B + buf * 64);
        const int cbase = ch * CHUNK_N + njOff;

#pragma unroll
        for (int nt = 0; nt < 2; nt++) {
            const int lcol = nt * 8 + g;
            const float bx = hbs[nt * 8 + 2 * t];
            const float by = hbs[nt * 8 + 2 * t + 1];
            float d0[4], d1[4], d2[4], d3[4];
#pragma unroll
            for (int mt = 0; mt < 4; mt++) { d0[mt]=bx; d1[mt]=by; d2[mt]=bx; d3[mt]=by; }

#pragma unroll
            for (int kb = 0; kb < KB; kb++) {
                uint32_t b0, b1;
                uint32_t addr = bB + lcol * ROWB + kb * 32 + t * 8;
                asm volatile("ld.shared.v2.u32 {%0,%1}, [%2];"
                             : "=r"(b0), "=r"(b1) : "r"(addr));
#pragma unroll
                for (int mt = 0; mt < 4; mt++) {
                    float dd[4] = {d0[mt], d1[mt], d2[mt], d3[mt]};
                    mma16816(dd, afr[mt][kb], b0, b1);
                    d0[mt]=dd[0]; d1[mt]=dd[1]; d2[mt]=dd[2]; d3[mt]=dd[3];
                }
            }

            // epilogue: pair-max on fma pipe, exact first-index tie semantics.
            // fmaxf + != keeps the earlier chunk/col on ties; d1>d0 strict keeps
            // the lower column within the pair on ties.
            const int c0 = cbase + nt * 8 + 2 * t;
#pragma unroll
            for (int mt = 0; mt < 4; mt++) {
                int se = 2 * mt, so = 2 * mt + 1;
                {
                    float pm = fmaxf(d0[mt], d1[mt]);          // FMNMX (fma)
                    float nb = fmaxf(best[se], pm);            // FMNMX (fma)
                    if (nb != best[se])                        // FSETP
                        bidx[se] = (d1[mt] > d0[mt]) ? c0 + 1 : c0;
                    best[se] = nb;
                }
                {
                    float pm = fmaxf(d2[mt], d3[mt]);
                    float nb = fmaxf(best[so], pm);
                    if (nb != best[so])
                        bidx[so] = (d3[mt] > d2[mt]) ? c0 + 1 : c0;
                    best[so] = nb;
                }
            }
        }

        if (ch + 2 < NCHUNK) stage(ch + 2, buf);
    }

    // ---- combine: quad shfl-reduce, then packed-key max across warps ----
#pragma unroll
    for (int s = 0; s < 8; s++) {
        unsigned int kh = ordf(best[s]);
        unsigned int kl = (unsigned int)(CS - 1 - bidx[s]);
#pragma unroll
        for (int o = 1; o < 4; o <<= 1) {
            unsigned int oh = __shfl_xor_sync(0xffffffffu, kh, o);
            unsigned int ol = __shfl_xor_sync(0xffffffffu, kl, o);
            if (oh > kh || (oh == kh && ol > kl)) { kh = oh; kl = ol; }
        }
        if (t == 0) {
            unsigned long long key = ((unsigned long long)kh << 32) | kl;
            atomicMax(&res[m_base + g + 8 * s], key);
        }
    }
    __syncthreads();

    if (tid < 128) {
        unsigned int low = (unsigned int)(res[tid] & 0xffffffffu);
        out[ctaTok + tid] = (float)(CS - 1 - (int)low);
    }
}

// ---------------- launch ----------------
extern "C" void kernel_launch(void* const* d_in, const int* in_sizes, int n_in,
                              void* d_out, int out_size) {
    const float* x  = nullptr;
    const float* W  = nullptr;
    const float* cb = nullptr;
    for (int i = 0; i < n_in; i++) {
        if      (in_sizes[i] == N_X)      x  = (const float*)d_in[i];
        else if (in_sizes[i] == N_W)      W  = (const float*)d_in[i];
        else if (in_sizes[i] == N_CB)     cb = (const float*)d_in[i];
        else if (in_sizes[i] == 4 * N_X)  x  = (const float*)d_in[i];
        else if (in_sizes[i] == 4 * N_W)  W  = (const float*)d_in[i];
        else if (in_sizes[i] == 4 * N_CB) cb = (const float*)d_in[i];
    }
    if (!x)  x  = (const float*)d_in[0];
    if (!W)  W  = (const float*)d_in[1];
    if (!cb) cb = (const float*)d_in[2];

    float* out = (float*)d_out;

    cudaFuncSetAttribute(scan_mma_kernel,
                         cudaFuncAttributeMaxDynamicSharedMemorySize, SCAN_SMEM);
    cudaFuncSetAttribute(fused_prep_kernel,
                         cudaFuncAttributeMaxDynamicSharedMemorySize, P1_SMEM);

    fused_prep_kernel<<<NB_FUSED, P1_THREADS, P1_SMEM>>>(x, W, cb);
    scan_mma_kernel<<<TOKENS / 128, SCAN_THREADS, SCAN_SMEM>>>(out);
}